// round 8
// baseline (speedup 1.0000x reference)
#include <cuda_runtime.h>
#include <cuda_bf16.h>
#include <cstdint>
#include <cstddef>

// ============================================================================
// out[8192,8192] = Q(x)[8192,2048] @ Q(w)[8192,2048]^T,  Q = e4m3 quant-dequant
// Legacy mma.sync m16n8k32 e4m3 (base-ISA; tcgen05 rejected by sm_103 target).
// R8 = R6 base (684us) + tile-boundary bubble shaving:
//   (1) 3-stage cp.async pipeline, wait_group 1  -> wait satisfied instantly
//   (2) k-step-0 LDSMs issued BEFORE the cp.async burst
//   (3) cp.async burst split across k-steps 0 and 1 (MIO pressure spreading)
// ============================================================================
static constexpr int M_TOTAL = 8192;
static constexpr int N_TOTAL = 8192;
static constexpr int K_TOTAL = 2048;

static constexpr int BM = 128, BN = 128, BK = 128;   // BK in fp8 bytes
static constexpr int K_TILES = K_TOTAL / BK;          // 16
static constexpr int STAGES = 3;
static constexpr int A_STAGE = BM * BK;               // 16384
static constexpr int B_STAGE = BN * BK;               // 16384
static constexpr int STAGE_BYTES = A_STAGE + B_STAGE; // 32768
static constexpr int SMEM_TOTAL = STAGES * STAGE_BYTES; // 98304 (2 CTA = 192KB)

// FP8 scratch (allocation-free: __device__ globals)
__device__ __align__(16) uint8_t g_Aq[(size_t)M_TOTAL * K_TOTAL];
__device__ __align__(16) uint8_t g_Wq[(size_t)N_TOTAL * K_TOTAL];

// ---------------------------------------------------------------------------
__device__ __forceinline__ uint32_t smem_u32(const void* p) {
    uint32_t a;
    asm("{ .reg .u64 t; cvta.to.shared.u64 t, %1; cvt.u32.u64 %0, t; }"
        : "=r"(a) : "l"(p));
    return a;
}

#define CP_ASYNC16(smem, gmem) \
    asm volatile("cp.async.cg.shared.global [%0], [%1], 16;" \
        :: "r"(smem), "l"(gmem) : "memory")
#define CP_COMMIT() asm volatile("cp.async.commit_group;" ::: "memory")
#define CP_WAIT(n)  asm volatile("cp.async.wait_group %0;" :: "n"(n) : "memory")

#define SWZ(off) ((off) ^ (((off) >> 3) & 0x70))

__device__ __forceinline__ void ldmatrix_x4(uint32_t* r, uint32_t addr) {
    asm volatile("ldmatrix.sync.aligned.m8n8.x4.shared.b16 {%0,%1,%2,%3}, [%4];"
        : "=r"(r[0]), "=r"(r[1]), "=r"(r[2]), "=r"(r[3]) : "r"(addr));
}

__device__ __forceinline__ void mma_e4m3(float* c, const uint32_t* a,
                                         const uint32_t* b) {
    asm volatile(
        "mma.sync.aligned.m16n8k32.row.col.f32.e4m3.e4m3.f32 "
        "{%0,%1,%2,%3}, {%4,%5,%6,%7}, {%8,%9}, {%0,%1,%2,%3};"
        : "+f"(c[0]), "+f"(c[1]), "+f"(c[2]), "+f"(c[3])
        : "r"(a[0]), "r"(a[1]), "r"(a[2]), "r"(a[3]),
          "r"(b[0]), "r"(b[1]));
}

// ============================================================================
// Fused quantization: fp32 -> e4m3 for BOTH matrices in one launch
// (keeps launches/call at 2 so ncu -s 5 -c 1 lands on the GEMM).
// ============================================================================
static constexpr int A_N4 = (M_TOTAL * K_TOTAL) / 4;
static constexpr int W_N4 = (N_TOTAL * K_TOTAL) / 4;

__global__ void __launch_bounds__(256) quant_both_kernel(
    const float* __restrict__ x, const float* __restrict__ w,
    const float* __restrict__ sx, const float* __restrict__ sw,
    uint8_t* __restrict__ aq, uint8_t* __restrict__ wq)
{
    int i = blockIdx.x * blockDim.x + threadIdx.x;
    const float* src;
    uint8_t* dst;
    float s;
    int j;
    if (i < A_N4) {
        src = x; dst = aq; s = __ldg(sx); j = i;
    } else {
        src = w; dst = wq; s = __ldg(sw); j = i - A_N4;
    }
    float4 v = reinterpret_cast<const float4*>(src)[j];
    uint16_t lo, hi;
    asm("cvt.rn.satfinite.e4m3x2.f32 %0, %1, %2;"
        : "=h"(lo) : "f"(v.y * s), "f"(v.x * s));
    asm("cvt.rn.satfinite.e4m3x2.f32 %0, %1, %2;"
        : "=h"(hi) : "f"(v.w * s), "f"(v.z * s));
    reinterpret_cast<uint32_t*>(dst)[j] = (uint32_t)lo | ((uint32_t)hi << 16);
}

// ============================================================================
// FP8 TN GEMM: CTA 128x128, 8 warps (4M x 2N), warp tile 32x64,
// 3-stage cp.async pipeline, XOR-only LDSM addressing.
// ============================================================================
__global__ void __launch_bounds__(256, 2) fp8_gemm_kernel(
    const uint8_t* __restrict__ Aq, const uint8_t* __restrict__ Wq,
    float* __restrict__ out,
    const float* __restrict__ sx, const float* __restrict__ sw)
{
    extern __shared__ char smem[];
    const uint32_t sbase = smem_u32(smem);
    const int tid  = threadIdx.x;
    const int lane = tid & 31;
    const int wid  = tid >> 5;
    const int warp_m = wid >> 1;   // 0..3
    const int warp_n = wid & 1;    // 0..1
    const int m0 = blockIdx.y * BM;
    const int n0 = blockIdx.x * BN;

    // ---- Precomputed cp.async mapping (constant across tiles) ----
    uint32_t st_swo[4];     // swizzled SMEM store offsets
    uint32_t ld_aoff[4];    // gmem byte offsets (advance by BK per tile)
    {
#pragma unroll
        for (int i = 0; i < 4; i++) {
            int c   = tid + i * 256;
            int row = c >> 3;
            int c16 = (c & 7) << 4;
            st_swo[i]  = SWZ((uint32_t)(row * BK + c16));
            ld_aoff[i] = (uint32_t)(row * K_TOTAL + c16);
        }
    }
    const uint8_t* agbase = Aq + (size_t)m0 * K_TOTAL;
    const uint8_t* bgbase = Wq + (size_t)n0 * K_TOTAL;

    auto load_half_A = [&](uint32_t sb, int kt) {
        const uint32_t koff = (uint32_t)kt * BK;
#pragma unroll
        for (int i = 0; i < 4; i++)
            CP_ASYNC16(sb + st_swo[i], agbase + ld_aoff[i] + koff);
    };
    auto load_half_B = [&](uint32_t sb, int kt) {
        const uint32_t koff = (uint32_t)kt * BK;
#pragma unroll
        for (int i = 0; i < 4; i++)
            CP_ASYNC16(sb + A_STAGE + st_swo[i], bgbase + ld_aoff[i] + koff);
    };

    // Prologue: tiles 0 and 1 in flight (one commit group each)
    load_half_A(sbase + 0 * STAGE_BYTES, 0);
    load_half_B(sbase + 0 * STAGE_BYTES, 0);
    CP_COMMIT();
    load_half_A(sbase + 1 * STAGE_BYTES, 1);
    load_half_B(sbase + 1 * STAGE_BYTES, 1);
    CP_COMMIT();

    float acc[2][8][4];
#pragma unroll
    for (int mt = 0; mt < 2; mt++)
#pragma unroll
        for (int nt = 0; nt < 8; nt++)
#pragma unroll
            for (int q = 0; q < 4; q++) acc[mt][nt][q] = 0.0f;

    // ---- Per-warp constant swizzled fragment offsets ----
    // Pre-swizzle offsets have bits[6:5]=0 and sbase is 1024-aligned, so
    // (base + SWZ(off)) ^ (s<<5) == base + SWZ(off + s*32).
    const int a_row = warp_m * 32 + (lane & 7) + ((lane >> 3) & 1) * 8;
    const int a_hi  = (lane >> 4) * 16;
    const int b_row = warp_n * 64 + (lane & 7) + (lane >> 4) * 8;
    const int b_hi  = ((lane >> 3) & 1) * 16;

    uint32_t a_sw[2], b_sw[4];
#pragma unroll
    for (int mt = 0; mt < 2; mt++)
        a_sw[mt] = SWZ((uint32_t)((a_row + mt * 16) * BK + a_hi));
#pragma unroll
    for (int p = 0; p < 4; p++)
        b_sw[p] = (uint32_t)A_STAGE + SWZ((uint32_t)((b_row + p * 16) * BK + b_hi));

    int slot = 0;       // slot of tile kt
    int wslot = 2;      // slot to write tile kt+2 into

    for (int kt = 0; kt < K_TILES; kt++) {
        // Tile kt's data was requested 2 tiles ago -> this wait is ~instant.
        CP_WAIT(1);
        __syncthreads();

        const uint32_t abase = sbase + (uint32_t)slot * STAGE_BYTES;
        const uint32_t wbase = sbase + (uint32_t)wslot * STAGE_BYTES;
        const bool more = (kt + 2 < K_TILES);

        uint32_t pa[2], pb[4];
#pragma unroll
        for (int mt = 0; mt < 2; mt++) pa[mt] = abase + a_sw[mt];
#pragma unroll
        for (int p = 0; p < 4; p++)    pb[p]  = abase + b_sw[p];

#pragma unroll
        for (int s = 0; s < BK / 32; s++) {       // 4 k-steps of 32 fp8
            const uint32_t sx32 = (uint32_t)(s << 5);
            // Fragments for this step FIRST (tensor pipe fed ASAP)...
            uint32_t af[2][4];
#pragma unroll
            for (int mt = 0; mt < 2; mt++)
                ldmatrix_x4(af[mt], pa[mt] ^ sx32);
            uint32_t bf[4][4];
#pragma unroll
            for (int p = 0; p < 4; p++)
                ldmatrix_x4(bf[p], pb[p] ^ sx32);
            // ...then spread the next-next tile's cp.async issue across
            // steps 0 and 1 (deadline is 2 tiles away).
            if (s == 0 && more) load_half_A(wbase, kt + 2);
            if (s == 1 && more) { load_half_B(wbase, kt + 2); CP_COMMIT(); }
#pragma unroll
            for (int mt = 0; mt < 2; mt++)
#pragma unroll
                for (int p = 0; p < 4; p++) {
                    mma_e4m3(acc[mt][2 * p + 0], af[mt], &bf[p][0]);
                    mma_e4m3(acc[mt][2 * p + 1], af[mt], &bf[p][2]);
                }
        }
        // Tail tiles issue no loads: commit an empty group to keep the
        // wait_group accounting aligned (wait 1 group per iteration).
        if (!more) CP_COMMIT();

        slot  = (slot  == STAGES - 1) ? 0 : slot + 1;
        wslot = (wslot == STAGES - 1) ? 0 : wslot + 1;
    }

    // Epilogue
    const float inv = 1.0f / (__ldg(sx) * __ldg(sw));
    const int r0 = m0 + warp_m * 32 + (lane >> 2);
    const int c0 = n0 + warp_n * 64 + (lane & 3) * 2;
#pragma unroll
    for (int mt = 0; mt < 2; mt++) {
#pragma unroll
        for (int nt = 0; nt < 8; nt++) {
            int row = r0 + mt * 16;
            int col = c0 + nt * 8;
            float2 v0 = { acc[mt][nt][0] * inv, acc[mt][nt][1] * inv };
            float2 v1 = { acc[mt][nt][2] * inv, acc[mt][nt][3] * inv };
            *reinterpret_cast<float2*>(out + (size_t)row * N_TOTAL + col) = v0;
            *reinterpret_cast<float2*>(out + (size_t)(row + 8) * N_TOTAL + col) = v1;
        }
    }
}

// ============================================================================
// kernel_launch
// ============================================================================
extern "C" void kernel_launch(void* const* d_in, const int* in_sizes, int n_in,
                              void* d_out, int out_size)
{
    const float* input  = (const float*)d_in[0];
    const float* weight = (const float*)d_in[1];
    const float* sx     = (const float*)d_in[2];  // input_scale_e4m3
    const float* sw     = (const float*)d_in[3];  // weight_scale_e4m3
    float* out = (float*)d_out;

    void* aq = nullptr;
    void* wq = nullptr;
    cudaGetSymbolAddress(&aq, g_Aq);
    cudaGetSymbolAddress(&wq, g_Wq);

    {
        int n4 = A_N4 + W_N4;
        quant_both_kernel<<<n4 / 256, 256>>>(input, weight, sx, sw,
                                             (uint8_t*)aq, (uint8_t*)wq);
    }

    cudaFuncSetAttribute(fp8_gemm_kernel,
                         cudaFuncAttributeMaxDynamicSharedMemorySize, SMEM_TOTAL);
    dim3 grid(N_TOTAL / BN, M_TOTAL / BM);
    fp8_gemm_kernel<<<grid, 256, SMEM_TOTAL>>>(
        (const uint8_t*)aq, (const uint8_t*)wq, out, sx, sw);
}

// round 9
// speedup vs baseline: 1.0616x; 1.0616x over previous
#include <cuda_runtime.h>
#include <cuda_bf16.h>
#include <cstdint>
#include <cstddef>

// ============================================================================
// out[8192,8192] = Q(x)[8192,2048] @ Q(w)[8192,2048]^T,  Q = e4m3 quant-dequant
// Legacy mma.sync m16n8k32 e4m3 (base-ISA; tcgen05 rejected by sm_103 target).
// R9 = R6 champion (684us) + two minimal deltas:
//   (1) tile-level pa/pb address fold -> 1 LOP3 per ldmatrix in the k-loop
//   (2) cp.async burst moved between step-0 LDSMs and step-0 MMAs
// No other structural changes (R5/R7/R8 restructures all regressed).
// ============================================================================
static constexpr int M_TOTAL = 8192;
static constexpr int N_TOTAL = 8192;
static constexpr int K_TOTAL = 2048;

static constexpr int BM = 128, BN = 128, BK = 128;   // BK in fp8 bytes
static constexpr int K_TILES = K_TOTAL / BK;          // 16
static constexpr int A_STAGE = BM * BK;               // 16384
static constexpr int B_STAGE = BN * BK;               // 16384
static constexpr int STAGE_BYTES = A_STAGE + B_STAGE; // 32768
static constexpr int SMEM_TOTAL = 2 * STAGE_BYTES;    // 65536

// FP8 scratch (allocation-free: __device__ globals)
__device__ __align__(16) uint8_t g_Aq[(size_t)M_TOTAL * K_TOTAL];
__device__ __align__(16) uint8_t g_Wq[(size_t)N_TOTAL * K_TOTAL];

// ---------------------------------------------------------------------------
__device__ __forceinline__ uint32_t smem_u32(const void* p) {
    uint32_t a;
    asm("{ .reg .u64 t; cvta.to.shared.u64 t, %1; cvt.u32.u64 %0, t; }"
        : "=r"(a) : "l"(p));
    return a;
}

#define CP_ASYNC16(smem, gmem) \
    asm volatile("cp.async.cg.shared.global [%0], [%1], 16;" \
        :: "r"(smem), "l"(gmem) : "memory")
#define CP_COMMIT() asm volatile("cp.async.commit_group;" ::: "memory")
#define CP_WAIT(n)  asm volatile("cp.async.wait_group %0;" :: "n"(n) : "memory")

#define SWZ(off) ((off) ^ (((off) >> 3) & 0x70))

__device__ __forceinline__ void ldmatrix_x4(uint32_t* r, uint32_t addr) {
    asm volatile("ldmatrix.sync.aligned.m8n8.x4.shared.b16 {%0,%1,%2,%3}, [%4];"
        : "=r"(r[0]), "=r"(r[1]), "=r"(r[2]), "=r"(r[3]) : "r"(addr));
}

__device__ __forceinline__ void mma_e4m3(float* c, const uint32_t* a,
                                         const uint32_t* b) {
    asm volatile(
        "mma.sync.aligned.m16n8k32.row.col.f32.e4m3.e4m3.f32 "
        "{%0,%1,%2,%3}, {%4,%5,%6,%7}, {%8,%9}, {%0,%1,%2,%3};"
        : "+f"(c[0]), "+f"(c[1]), "+f"(c[2]), "+f"(c[3])
        : "r"(a[0]), "r"(a[1]), "r"(a[2]), "r"(a[3]),
          "r"(b[0]), "r"(b[1]));
}

// ============================================================================
// Fused quantization: fp32 -> e4m3 for BOTH matrices in one launch
// (keeps launches/call at 2 so ncu -s 5 -c 1 lands on the GEMM).
// ============================================================================
static constexpr int A_N4 = (M_TOTAL * K_TOTAL) / 4;
static constexpr int W_N4 = (N_TOTAL * K_TOTAL) / 4;

__global__ void __launch_bounds__(256) quant_both_kernel(
    const float* __restrict__ x, const float* __restrict__ w,
    const float* __restrict__ sx, const float* __restrict__ sw,
    uint8_t* __restrict__ aq, uint8_t* __restrict__ wq)
{
    int i = blockIdx.x * blockDim.x + threadIdx.x;
    const float* src;
    uint8_t* dst;
    float s;
    int j;
    if (i < A_N4) {
        src = x; dst = aq; s = __ldg(sx); j = i;
    } else {
        src = w; dst = wq; s = __ldg(sw); j = i - A_N4;
    }
    float4 v = reinterpret_cast<const float4*>(src)[j];
    uint16_t lo, hi;
    asm("cvt.rn.satfinite.e4m3x2.f32 %0, %1, %2;"
        : "=h"(lo) : "f"(v.y * s), "f"(v.x * s));
    asm("cvt.rn.satfinite.e4m3x2.f32 %0, %1, %2;"
        : "=h"(hi) : "f"(v.w * s), "f"(v.z * s));
    reinterpret_cast<uint32_t*>(dst)[j] = (uint32_t)lo | ((uint32_t)hi << 16);
}

// ============================================================================
// FP8 TN GEMM: CTA 128x128, 8 warps (4M x 2N), warp tile 32x64,
// 2-stage cp.async double buffer, XOR-only LDSM addressing.
// ============================================================================
__global__ void __launch_bounds__(256, 2) fp8_gemm_kernel(
    const uint8_t* __restrict__ Aq, const uint8_t* __restrict__ Wq,
    float* __restrict__ out,
    const float* __restrict__ sx, const float* __restrict__ sw)
{
    extern __shared__ char smem[];
    const uint32_t sbase = smem_u32(smem);
    const int tid  = threadIdx.x;
    const int lane = tid & 31;
    const int wid  = tid >> 5;
    const int warp_m = wid >> 1;   // 0..3
    const int warp_n = wid & 1;    // 0..1
    const int m0 = blockIdx.y * BM;
    const int n0 = blockIdx.x * BN;

    // ---- Precomputed cp.async mapping (constant across tiles) ----
    uint32_t st_swo[4];     // swizzled SMEM store offsets
    uint32_t ld_aoff[4];    // gmem byte offsets (advance by BK per tile)
    {
#pragma unroll
        for (int i = 0; i < 4; i++) {
            int c   = tid + i * 256;
            int row = c >> 3;
            int c16 = (c & 7) << 4;
            st_swo[i]  = SWZ((uint32_t)(row * BK + c16));
            ld_aoff[i] = (uint32_t)(row * K_TOTAL + c16);
        }
    }
    const uint8_t* agbase = Aq + (size_t)m0 * K_TOTAL;
    const uint8_t* bgbase = Wq + (size_t)n0 * K_TOTAL;

    auto load_stage = [&](int slot, int kt) {
        const uint32_t abase = sbase + slot * STAGE_BYTES;
        const uint32_t koff  = (uint32_t)kt * BK;
#pragma unroll
        for (int i = 0; i < 4; i++) {
            CP_ASYNC16(abase + st_swo[i],           agbase + ld_aoff[i] + koff);
            CP_ASYNC16(abase + A_STAGE + st_swo[i], bgbase + ld_aoff[i] + koff);
        }
    };

    // Prologue
    load_stage(0, 0);
    CP_COMMIT();

    float acc[2][8][4];
#pragma unroll
    for (int mt = 0; mt < 2; mt++)
#pragma unroll
        for (int nt = 0; nt < 8; nt++)
#pragma unroll
            for (int q = 0; q < 4; q++) acc[mt][nt][q] = 0.0f;

    // ---- Per-warp constant swizzled fragment offsets ----
    // Pre-swizzle offsets have bits[6:5]=0 and sbase is 1024-aligned, so
    // (base + SWZ(off)) ^ (s<<5) == base + SWZ(off + s*32).
    const int a_row = warp_m * 32 + (lane & 7) + ((lane >> 3) & 1) * 8;
    const int a_hi  = (lane >> 4) * 16;
    const int b_row = warp_n * 64 + (lane & 7) + (lane >> 4) * 8;
    const int b_hi  = ((lane >> 3) & 1) * 16;

    uint32_t a_sw[2], b_sw[4];
#pragma unroll
    for (int mt = 0; mt < 2; mt++)
        a_sw[mt] = SWZ((uint32_t)((a_row + mt * 16) * BK + a_hi));
#pragma unroll
    for (int p = 0; p < 4; p++)
        b_sw[p] = (uint32_t)A_STAGE + SWZ((uint32_t)((b_row + p * 16) * BK + b_hi));

    for (int kt = 0; kt < K_TILES; kt++) {
        CP_WAIT(0);
        __syncthreads();

        const uint32_t abase = sbase + (kt & 1) * STAGE_BYTES;
        // Tile-level full addresses (6 adds per tile, then XOR-only)
        uint32_t pa[2], pb[4];
#pragma unroll
        for (int mt = 0; mt < 2; mt++) pa[mt] = abase + a_sw[mt];
#pragma unroll
        for (int p = 0; p < 4; p++)    pb[p]  = abase + b_sw[p];

#pragma unroll
        for (int s = 0; s < BK / 32; s++) {       // 4 k-steps of 32 fp8
            const uint32_t sx32 = (uint32_t)(s << 5);
            uint32_t af[2][4];
#pragma unroll
            for (int mt = 0; mt < 2; mt++)
                ldmatrix_x4(af[mt], pa[mt] ^ sx32);
            uint32_t bf[4][4];
#pragma unroll
            for (int p = 0; p < 4; p++)
                ldmatrix_x4(bf[p], pb[p] ^ sx32);
            // Next tile's loads issued inside step-0's LDSM->MMA latency
            // window (pure reorder vs R6; same wait/commit accounting).
            if (s == 0 && kt + 1 < K_TILES) {
                load_stage((kt + 1) & 1, kt + 1);
                CP_COMMIT();
            }
#pragma unroll
            for (int mt = 0; mt < 2; mt++)
#pragma unroll
                for (int p = 0; p < 4; p++) {
                    mma_e4m3(acc[mt][2 * p + 0], af[mt], &bf[p][0]);
                    mma_e4m3(acc[mt][2 * p + 1], af[mt], &bf[p][2]);
                }
        }
    }

    // Epilogue
    const float inv = 1.0f / (__ldg(sx) * __ldg(sw));
    const int r0 = m0 + warp_m * 32 + (lane >> 2);
    const int c0 = n0 + warp_n * 64 + (lane & 3) * 2;
#pragma unroll
    for (int mt = 0; mt < 2; mt++) {
#pragma unroll
        for (int nt = 0; nt < 8; nt++) {
            int row = r0 + mt * 16;
            int col = c0 + nt * 8;
            float2 v0 = { acc[mt][nt][0] * inv, acc[mt][nt][1] * inv };
            float2 v1 = { acc[mt][nt][2] * inv, acc[mt][nt][3] * inv };
            *reinterpret_cast<float2*>(out + (size_t)row * N_TOTAL + col) = v0;
            *reinterpret_cast<float2*>(out + (size_t)(row + 8) * N_TOTAL + col) = v1;
        }
    }
}

// ============================================================================
// kernel_launch
// ============================================================================
extern "C" void kernel_launch(void* const* d_in, const int* in_sizes, int n_in,
                              void* d_out, int out_size)
{
    const float* input  = (const float*)d_in[0];
    const float* weight = (const float*)d_in[1];
    const float* sx     = (const float*)d_in[2];  // input_scale_e4m3
    const float* sw     = (const float*)d_in[3];  // weight_scale_e4m3
    float* out = (float*)d_out;

    void* aq = nullptr;
    void* wq = nullptr;
    cudaGetSymbolAddress(&aq, g_Aq);
    cudaGetSymbolAddress(&wq, g_Wq);

    {
        int n4 = A_N4 + W_N4;
        quant_both_kernel<<<n4 / 256, 256>>>(input, weight, sx, sw,
                                             (uint8_t*)aq, (uint8_t*)wq);
    }

    cudaFuncSetAttribute(fp8_gemm_kernel,
                         cudaFuncAttributeMaxDynamicSharedMemorySize, SMEM_TOTAL);
    dim3 grid(N_TOTAL / BN, M_TOTAL / BM);
    fp8_gemm_kernel<<<grid, 256, SMEM_TOTAL>>>(
        (const uint8_t*)aq, (const uint8_t*)wq, out, sx, sw);
}

// round 10
// speedup vs baseline: 1.0981x; 1.0344x over previous
#include <cuda_runtime.h>
#include <cuda_bf16.h>
#include <cstdint>
#include <cstddef>

// ============================================================================
// out[8192,8192] = Q(x)[8192,2048] @ Q(w)[8192,2048]^T,  Q = e4m3 quant-dequant
// Legacy mma.sync m16n8k32 e4m3 (base-ISA; tcgen05 rejected by sm_103 target).
// R10 = R6 champion body + register diet:
//   - cp.async offset arrays (8 regs) replaced by immediate address offsets
//     (strides are compile-time: smem +4096/chunk, gmem +32*K/chunk)
//   - gmem tile pointers advanced incrementally (+BK per tile)
//   - mainloop LDSM addressing byte-identical to R6 (no pa/pb fold: that
//     added live regs at the 128-reg cap and regressed in R7/R9)
// ============================================================================
static constexpr int M_TOTAL = 8192;
static constexpr int N_TOTAL = 8192;
static constexpr int K_TOTAL = 2048;

static constexpr int BM = 128, BN = 128, BK = 128;   // BK in fp8 bytes
static constexpr int K_TILES = K_TOTAL / BK;          // 16
static constexpr int A_STAGE = BM * BK;               // 16384
static constexpr int B_STAGE = BN * BK;               // 16384
static constexpr int STAGE_BYTES = A_STAGE + B_STAGE; // 32768
static constexpr int SMEM_TOTAL = 2 * STAGE_BYTES;    // 65536

// FP8 scratch (allocation-free: __device__ globals)
__device__ __align__(16) uint8_t g_Aq[(size_t)M_TOTAL * K_TOTAL];
__device__ __align__(16) uint8_t g_Wq[(size_t)N_TOTAL * K_TOTAL];

// ---------------------------------------------------------------------------
__device__ __forceinline__ uint32_t smem_u32(const void* p) {
    uint32_t a;
    asm("{ .reg .u64 t; cvta.to.shared.u64 t, %1; cvt.u32.u64 %0, t; }"
        : "=r"(a) : "l"(p));
    return a;
}

// cp.async with compile-time address offsets (keeps offsets out of registers)
#define CP_ASYNC16_OFF(smem, soff, gmem, goff) \
    asm volatile("cp.async.cg.shared.global [%0+%2], [%1+%3], 16;" \
        :: "r"(smem), "l"(gmem), "n"(soff), "n"(goff) : "memory")
#define CP_COMMIT() asm volatile("cp.async.commit_group;" ::: "memory")
#define CP_WAIT(n)  asm volatile("cp.async.wait_group %0;" :: "n"(n) : "memory")

#define SWZ(off) ((off) ^ (((off) >> 3) & 0x70))

__device__ __forceinline__ void ldmatrix_x4(uint32_t* r, uint32_t addr) {
    asm volatile("ldmatrix.sync.aligned.m8n8.x4.shared.b16 {%0,%1,%2,%3}, [%4];"
        : "=r"(r[0]), "=r"(r[1]), "=r"(r[2]), "=r"(r[3]) : "r"(addr));
}

__device__ __forceinline__ void mma_e4m3(float* c, const uint32_t* a,
                                         const uint32_t* b) {
    asm volatile(
        "mma.sync.aligned.m16n8k32.row.col.f32.e4m3.e4m3.f32 "
        "{%0,%1,%2,%3}, {%4,%5,%6,%7}, {%8,%9}, {%0,%1,%2,%3};"
        : "+f"(c[0]), "+f"(c[1]), "+f"(c[2]), "+f"(c[3])
        : "r"(a[0]), "r"(a[1]), "r"(a[2]), "r"(a[3]),
          "r"(b[0]), "r"(b[1]));
}

// ============================================================================
// Fused quantization: fp32 -> e4m3 for BOTH matrices in one launch
// (keeps launches/call at 2 so ncu -s 5 -c 1 lands on the GEMM).
// ============================================================================
static constexpr int A_N4 = (M_TOTAL * K_TOTAL) / 4;
static constexpr int W_N4 = (N_TOTAL * K_TOTAL) / 4;

__global__ void __launch_bounds__(256) quant_both_kernel(
    const float* __restrict__ x, const float* __restrict__ w,
    const float* __restrict__ sx, const float* __restrict__ sw,
    uint8_t* __restrict__ aq, uint8_t* __restrict__ wq)
{
    int i = blockIdx.x * blockDim.x + threadIdx.x;
    const float* src;
    uint8_t* dst;
    float s;
    int j;
    if (i < A_N4) {
        src = x; dst = aq; s = __ldg(sx); j = i;
    } else {
        src = w; dst = wq; s = __ldg(sw); j = i - A_N4;
    }
    float4 v = reinterpret_cast<const float4*>(src)[j];
    uint16_t lo, hi;
    asm("cvt.rn.satfinite.e4m3x2.f32 %0, %1, %2;"
        : "=h"(lo) : "f"(v.y * s), "f"(v.x * s));
    asm("cvt.rn.satfinite.e4m3x2.f32 %0, %1, %2;"
        : "=h"(hi) : "f"(v.w * s), "f"(v.z * s));
    reinterpret_cast<uint32_t*>(dst)[j] = (uint32_t)lo | ((uint32_t)hi << 16);
}

// ============================================================================
// FP8 TN GEMM: CTA 128x128, 8 warps (4M x 2N), warp tile 32x64,
// 2-stage cp.async double buffer, XOR-only LDSM addressing (R6 form).
// ============================================================================
__global__ void __launch_bounds__(256, 2) fp8_gemm_kernel(
    const uint8_t* __restrict__ Aq, const uint8_t* __restrict__ Wq,
    float* __restrict__ out,
    const float* __restrict__ sx, const float* __restrict__ sw)
{
    extern __shared__ char smem[];
    const uint32_t sbase = smem_u32(smem);
    const int tid  = threadIdx.x;
    const int lane = tid & 31;
    const int wid  = tid >> 5;
    const int warp_m = wid >> 1;   // 0..3
    const int warp_n = wid & 1;    // 0..1
    const int m0 = blockIdx.y * BM;
    const int n0 = blockIdx.x * BN;

    // ---- cp.async mapping, arithmetic-progression form ----
    // chunk c = tid + i*256: row_i = row_0 + 32*i (since 256/8 = 32),
    // c16 identical for all i. Hence:
    //   gmem offset_i = offset_0 + i * 32 * K_TOTAL   (immediate)
    //   smem offset_i = SWZ(off_0) + i * 32 * BK      (immediate; i*4096 has
    //       zero bits in [7:9], so SWZ distributes over the add)
    const int row0 = tid >> 3;
    const int c16  = (tid & 7) << 4;
    const uint32_t st0 = SWZ((uint32_t)(row0 * BK + c16));   // 1 reg
    // Incrementally-advanced gmem pointers (base of this thread's chunk 0)
    const uint8_t* agp = Aq + (size_t)(m0 + row0) * K_TOTAL + c16;
    const uint8_t* bgp = Wq + (size_t)(n0 + row0) * K_TOTAL + c16;

    static constexpr int GSTRIDE = 32 * K_TOTAL;   // 65536
    static constexpr int SSTRIDE = 32 * BK;        // 4096

    auto load_stage = [&](uint32_t slot_base) {
        const uint32_t sa = slot_base + st0;
        const uint32_t sb = sa + (uint32_t)A_STAGE;
        CP_ASYNC16_OFF(sa, 0 * SSTRIDE, agp, 0 * GSTRIDE);
        CP_ASYNC16_OFF(sa, 1 * SSTRIDE, agp, 1 * GSTRIDE);
        CP_ASYNC16_OFF(sa, 2 * SSTRIDE, agp, 2 * GSTRIDE);
        CP_ASYNC16_OFF(sa, 3 * SSTRIDE, agp, 3 * GSTRIDE);
        CP_ASYNC16_OFF(sb, 0 * SSTRIDE, bgp, 0 * GSTRIDE);
        CP_ASYNC16_OFF(sb, 1 * SSTRIDE, bgp, 1 * GSTRIDE);
        CP_ASYNC16_OFF(sb, 2 * SSTRIDE, bgp, 2 * GSTRIDE);
        CP_ASYNC16_OFF(sb, 3 * SSTRIDE, bgp, 3 * GSTRIDE);
        // Advance tile pointers (one 64-bit add each per tile)
        agp += BK;
        bgp += BK;
    };

    // Prologue: tile 0 -> slot 0
    load_stage(sbase);
    CP_COMMIT();

    float acc[2][8][4];
#pragma unroll
    for (int mt = 0; mt < 2; mt++)
#pragma unroll
        for (int nt = 0; nt < 8; nt++)
#pragma unroll
            for (int q = 0; q < 4; q++) acc[mt][nt][q] = 0.0f;

    // ---- Per-warp constant swizzled fragment offsets (R6 form) ----
    // Pre-swizzle offsets have bits[6:5]=0 and sbase is 1024-aligned, so
    // (base + SWZ(off)) ^ (s<<5) == base + SWZ(off + s*32).
    const int a_row = warp_m * 32 + (lane & 7) + ((lane >> 3) & 1) * 8;
    const int a_hi  = (lane >> 4) * 16;
    const int b_row = warp_n * 64 + (lane & 7) + (lane >> 4) * 8;
    const int b_hi  = ((lane >> 3) & 1) * 16;

    uint32_t a_sw[2], b_sw[4];
#pragma unroll
    for (int mt = 0; mt < 2; mt++)
        a_sw[mt] = SWZ((uint32_t)((a_row + mt * 16) * BK + a_hi));
#pragma unroll
    for (int p = 0; p < 4; p++)
        b_sw[p] = (uint32_t)A_STAGE + SWZ((uint32_t)((b_row + p * 16) * BK + b_hi));

    for (int kt = 0; kt < K_TILES; kt++) {
        CP_WAIT(0);
        __syncthreads();

        if (kt + 1 < K_TILES) {
            load_stage(sbase + (uint32_t)(((kt + 1) & 1) * STAGE_BYTES));
            CP_COMMIT();
        }

        const uint32_t abase = sbase + (uint32_t)((kt & 1) * STAGE_BYTES);

#pragma unroll
        for (int s = 0; s < BK / 32; s++) {       // 4 k-steps of 32 fp8
            const uint32_t sx32 = (uint32_t)(s << 5);
            uint32_t af[2][4];
#pragma unroll
            for (int mt = 0; mt < 2; mt++)
                ldmatrix_x4(af[mt], abase + (a_sw[mt] ^ sx32));
            uint32_t bf[4][4];
#pragma unroll
            for (int p = 0; p < 4; p++)
                ldmatrix_x4(bf[p], abase + (b_sw[p] ^ sx32));
#pragma unroll
            for (int mt = 0; mt < 2; mt++)
#pragma unroll
                for (int p = 0; p < 4; p++) {
                    mma_e4m3(acc[mt][2 * p + 0], af[mt], &bf[p][0]);
                    mma_e4m3(acc[mt][2 * p + 1], af[mt], &bf[p][2]);
                }
        }
    }

    // Epilogue
    const float inv = 1.0f / (__ldg(sx) * __ldg(sw));
    const int r0 = m0 + warp_m * 32 + (lane >> 2);
    const int c0 = n0 + warp_n * 64 + (lane & 3) * 2;
#pragma unroll
    for (int mt = 0; mt < 2; mt++) {
#pragma unroll
        for (int nt = 0; nt < 8; nt++) {
            int row = r0 + mt * 16;
            int col = c0 + nt * 8;
            float2 v0 = { acc[mt][nt][0] * inv, acc[mt][nt][1] * inv };
            float2 v1 = { acc[mt][nt][2] * inv, acc[mt][nt][3] * inv };
            *reinterpret_cast<float2*>(out + (size_t)row * N_TOTAL + col) = v0;
            *reinterpret_cast<float2*>(out + (size_t)(row + 8) * N_TOTAL + col) = v1;
        }
    }
}

// ============================================================================
// kernel_launch
// ============================================================================
extern "C" void kernel_launch(void* const* d_in, const int* in_sizes, int n_in,
                              void* d_out, int out_size)
{
    const float* input  = (const float*)d_in[0];
    const float* weight = (const float*)d_in[1];
    const float* sx     = (const float*)d_in[2];  // input_scale_e4m3
    const float* sw     = (const float*)d_in[3];  // weight_scale_e4m3
    float* out = (float*)d_out;

    void* aq = nullptr;
    void* wq = nullptr;
    cudaGetSymbolAddress(&aq, g_Aq);
    cudaGetSymbolAddress(&wq, g_Wq);

    {
        int n4 = A_N4 + W_N4;
        quant_both_kernel<<<n4 / 256, 256>>>(input, weight, sx, sw,
                                             (uint8_t*)aq, (uint8_t*)wq);
    }

    cudaFuncSetAttribute(fp8_gemm_kernel,
                         cudaFuncAttributeMaxDynamicSharedMemorySize, SMEM_TOTAL);
    dim3 grid(N_TOTAL / BN, M_TOTAL / BM);
    fp8_gemm_kernel<<<grid, 256, SMEM_TOTAL>>>(
        (const uint8_t*)aq, (const uint8_t*)wq, out, sx, sw);
}